// round 5
// baseline (speedup 1.0000x reference)
#include <cuda_runtime.h>
#include <cstdint>

#define DINLINE __device__ __forceinline__

constexpr int T   = 2048;   // tokens
constexpr int H   = 2048;   // hidden
constexpr int NE  = 16;     // experts
constexpr int IE  = 512;    // expert intermediate
constexpr int ISZ = 2048;   // shared intermediate
constexpr int MAXROWS  = 6144;  // 4096 pairs + 16*128 tile padding
constexpr int MAXTILES = 48;

constexpr int BM = 128, BN = 128, BK = 16;

// ---------------- scratch (device globals; no allocation allowed) ------------
__device__ int   g_counts[NE];
__device__ int   g_off[NE];
__device__ int   g_cursor[NE];
__device__ int   g_tile_expert[MAXTILES];
__device__ int   g_rowtok[MAXROWS];
__device__ float g_roww[MAXROWS];
__device__ int   g_sel[T * 2];
__device__ float g_wk[T * 2];
__device__ int   g_pairslot[T * 2];
__device__ float g_gate[T];
__device__ float g_mid12[(size_t)MAXROWS * 1024];   // expert gate|up raw
__device__ float g_hmid [(size_t)MAXROWS * IE];     // expert swiglu * weight
__device__ float g_outp [(size_t)MAXROWS * H];      // expert partial outputs
__device__ float g_smid [(size_t)T * 2 * ISZ];      // shared gate|up raw
__device__ float g_shmid[(size_t)T * ISZ];          // shared swiglu

// ---------------- small kernels ---------------------------------------------
__global__ void zero_init() {
    int i = blockIdx.x * blockDim.x + threadIdx.x;
    if (i < MAXROWS) { g_rowtok[i] = -1; g_roww[i] = 0.f; }
    if (i < NE) g_counts[i] = 0;
}

// One warp per token: 16 router logits + 1 shared-gate logit.
__global__ void router_k(const float* __restrict__ X,
                         const float* __restrict__ GW,
                         const float* __restrict__ SGW) {
    __shared__ float Ws[17][128];
    int lane = threadIdx.x & 31, warp = threadIdx.x >> 5;
    int t = blockIdx.x * 4 + warp;

    float acc[17];
#pragma unroll
    for (int e = 0; e < 17; e++) acc[e] = 0.f;

    for (int k0 = 0; k0 < H; k0 += 128) {
        __syncthreads();
        for (int j = threadIdx.x; j < 17 * 128; j += 128) {
            int e = j >> 7, kk = j & 127;
            Ws[e][kk] = (e < 16) ? GW[e * H + k0 + kk] : SGW[k0 + kk];
        }
        __syncthreads();
        float xv[4];
#pragma unroll
        for (int i = 0; i < 4; i++) xv[i] = X[(size_t)t * H + k0 + i * 32 + lane];
#pragma unroll
        for (int e = 0; e < 17; e++) {
#pragma unroll
            for (int i = 0; i < 4; i++) acc[e] += xv[i] * Ws[e][i * 32 + lane];
        }
    }
#pragma unroll
    for (int e = 0; e < 17; e++) {
        float v = acc[e];
#pragma unroll
        for (int o = 16; o > 0; o >>= 1) v += __shfl_xor_sync(0xffffffffu, v, o);
        acc[e] = v;
    }
    if (lane == 0) {
        int i1 = 0;
        for (int e = 1; e < 16; e++) if (acc[e] > acc[i1]) i1 = e;
        int i2 = (i1 == 0) ? 1 : 0;
        for (int e = 0; e < 16; e++) if (e != i1 && acc[e] > acc[i2]) i2 = e;
        float m  = acc[i1];
        float e1 = expf(acc[i1] - m), e2 = expf(acc[i2] - m);
        float s  = e1 + e2;
        g_sel[t * 2] = i1;  g_sel[t * 2 + 1] = i2;
        g_wk [t * 2] = e1 / s;  g_wk [t * 2 + 1] = e2 / s;
        atomicAdd(&g_counts[i1], 1);
        atomicAdd(&g_counts[i2], 1);
        g_gate[t] = 1.f / (1.f + expf(-acc[16]));
    }
}

__global__ void offsets_k() {
    if (threadIdx.x == 0 && blockIdx.x == 0) {
        int off = 0, tile = 0;
        for (int e = 0; e < NE; e++) {
            g_off[e] = off;
            g_cursor[e] = 0;
            int nt = (g_counts[e] + BM - 1) / BM;
            for (int j = 0; j < nt; j++) g_tile_expert[tile++] = e;
            off += nt * BM;
        }
        for (; tile < MAXTILES; tile++) g_tile_expert[tile] = -1;
    }
}

__global__ void scatter_k() {
    int t = blockIdx.x * blockDim.x + threadIdx.x;
    if (t >= T) return;
#pragma unroll
    for (int k = 0; k < 2; k++) {
        int e   = g_sel[t * 2 + k];
        int pos = atomicAdd(&g_cursor[e], 1);
        int row = g_off[e] + pos;
        g_rowtok[row] = t;
        g_roww[row]   = g_wk[t * 2 + k];
        g_pairslot[t * 2 + k] = row;
    }
}

// ---------------- tf32 MMA GEMM (fragment-native smem layout) -----------------
DINLINE unsigned cvt_tf32(float f) {
    unsigned u;
    asm("cvt.rna.tf32.f32 %0, %1;" : "=r"(u) : "f"(f));
    return u;
}
DINLINE void mma8(float* c, const unsigned* a, unsigned b0, unsigned b1) {
    asm volatile(
        "mma.sync.aligned.m16n8k8.row.col.f32.tf32.tf32.f32 "
        "{%0,%1,%2,%3}, {%4,%5,%6,%7}, {%8,%9}, {%0,%1,%2,%3};"
        : "+f"(c[0]), "+f"(c[1]), "+f"(c[2]), "+f"(c[3])
        : "r"(a[0]), "r"(a[1]), "r"(a[2]), "r"(a[3]), "r"(b0), "r"(b1));
}

// Smem layout (per 128x16 tile, stored as tf32 words):
//  A quads: unit = g*64 + gq*8 + ((kk*4+tg)^gq), quad = {A[16g+gq][8kk+tg],
//           A[16g+8+gq][8kk+tg], A[16g+gq][8kk+tg+4], A[16g+8+gq][8kk+tg+4]}
//  B quads: unit = n*4 + tg, quad = {B[n][tg], B[n][tg+4], B[n][tg+8], B[n][tg+12]}
// Both fragment loads are single LDS.128, optimal 4-phase.

// MODE 0: expert gate/up  C[row,1024] = Xg[row,H]   * [w1;w3]^T   (gathered rows)
// MODE 1: expert down     C[row,H]    = hmid[row,I] * w2^T
// MODE 2: shared gate/up  C[t,4096]   = X[t,H]      * [wsg;wsu]^T
// MODE 3: shared down     out[t,H]    = gate[t] * (shmid[t,IS] * wsd^T)
template <int MODE>
__global__ void __launch_bounds__(256, 1)
gemm_k(const float* __restrict__ Ain, const float* __restrict__ Wa,
       const float* __restrict__ Wb, float* __restrict__ Out) {
    __shared__ __align__(16) unsigned As[2][2048];
    __shared__ __align__(16) unsigned Bs[2][2048];

    int by = blockIdx.y, bx = blockIdx.x;
    int e = 0;
    if (MODE == 0 || MODE == 1) {
        e = g_tile_expert[by];
        if (e < 0) return;
    }
    const int m0 = by * BM, n0 = bx * BN;
    const int tid = threadIdx.x;

    constexpr int KS = (MODE == 1) ? IE : ((MODE == 3) ? ISZ : H);
    constexpr int ksteps = KS / BK;

    // ---- load assignment: idx = i*256 + tid over [part][row 0..127][kc 0..3]
    //      kc = idx&3, row = (idx>>2)&127, part = idx>>9 (0=A, 1=B)
    const float* gp[4];
    int   srow[4];
    int   spart[4];
#pragma unroll
    for (int i = 0; i < 4; i++) {
        int idx  = i * 256 + tid;
        int kc   = idx & 3;
        int row  = (idx >> 2) & 127;
        int part = idx >> 9;
        srow[i] = row;  spart[i] = part;
        const float* base = nullptr;
        if (part == 0) {
            if constexpr (MODE == 0) {
                int tok = g_rowtok[m0 + row];
                base = (tok >= 0) ? (Ain + (size_t)tok * H) : nullptr;
            } else if constexpr (MODE == 1) {
                base = g_hmid + (size_t)(m0 + row) * IE;
            } else if constexpr (MODE == 2) {
                base = Ain + (size_t)(m0 + row) * H;
            } else {
                base = g_shmid + (size_t)(m0 + row) * ISZ;
            }
        } else {
            int n = n0 + row;
            if constexpr (MODE == 0)
                base = (n < IE) ? (Wa + ((size_t)e * IE + n) * H)
                                : (Wb + ((size_t)e * IE + (n - IE)) * H);
            else if constexpr (MODE == 1)
                base = Wa + ((size_t)e * H + n) * IE;
            else if constexpr (MODE == 2)
                base = (n < ISZ) ? (Wa + (size_t)n * H) : (Wb + (size_t)(n - ISZ) * H);
            else
                base = Wa + (size_t)n * ISZ;
        }
        gp[i] = base ? (base + kc * 4) : nullptr;
    }
    // precomputed smem word offsets for the 4 scalar stores of each float4
    int soff[4][4];
#pragma unroll
    for (int i = 0; i < 4; i++) {
        int idx = i * 256 + tid;
        int kc  = idx & 3;
        int row = srow[i];
        if (spart[i] == 0) {
            int g = row >> 4, gq = row & 7, rowhigh = (row >> 3) & 1;
            int kk = kc >> 1, khalf = kc & 1;
            int pos = khalf * 2 + rowhigh;
#pragma unroll
            for (int tg = 0; tg < 4; tg++) {
                int unit = g * 64 + gq * 8 + ((kk * 4 + tg) ^ gq);
                soff[i][tg] = unit * 4 + pos;
            }
        } else {
#pragma unroll
            for (int tg = 0; tg < 4; tg++)
                soff[i][tg] = (row * 4 + tg) * 4 + kc;   // pos = kc
        }
    }

    float acc[4][4][4];
#pragma unroll
    for (int a = 0; a < 4; a++)
#pragma unroll
        for (int b = 0; b < 4; b++)
#pragma unroll
            for (int c = 0; c < 4; c++) acc[a][b][c] = 0.f;

    const int wid = tid >> 5, lane = tid & 31;
    const int wr = wid >> 2, wc = wid & 3;      // 2x4 warp grid, 64x32 warp tile
    const int gq = lane >> 2, tg = lane & 3;

    // fragment load offsets (words)
    int afw[4][2];   // [mi][kk]
#pragma unroll
    for (int mi = 0; mi < 4; mi++)
#pragma unroll
        for (int kk = 0; kk < 2; kk++) {
            int g = wr * 4 + mi;
            afw[mi][kk] = (g * 64 + gq * 8 + ((kk * 4 + tg) ^ gq)) * 4;
        }
    int bfw[4];      // [ni]
#pragma unroll
    for (int ni = 0; ni < 4; ni++)
        bfw[ni] = ((wc * 32 + ni * 8) * 4 + lane) * 4;

    // ---- prologue: fill stage 0 ----
    {
#pragma unroll
        for (int i = 0; i < 4; i++) {
            float4 v = gp[i] ? *reinterpret_cast<const float4*>(gp[i])
                             : make_float4(0.f, 0.f, 0.f, 0.f);
            unsigned* dst = (spart[i] == 0) ? As[0] : Bs[0];
            dst[soff[i][0]] = cvt_tf32(v.x);
            dst[soff[i][1]] = cvt_tf32(v.y);
            dst[soff[i][2]] = cvt_tf32(v.z);
            dst[soff[i][3]] = cvt_tf32(v.w);
        }
    }
    __syncthreads();

#pragma unroll 1
    for (int kt = 0; kt < ksteps; ++kt) {
        int cur = kt & 1;
        bool pf = (kt + 1) < ksteps;

        // prefetch next stage's global data (latency overlaps compute)
        float4 pv[4];
        if (pf) {
            size_t ko = (size_t)(kt + 1) * BK;
#pragma unroll
            for (int i = 0; i < 4; i++)
                pv[i] = gp[i] ? *reinterpret_cast<const float4*>(gp[i] + ko)
                              : make_float4(0.f, 0.f, 0.f, 0.f);
        }

        // compute on current buffer
        uint4 bq[4];
#pragma unroll
        for (int ni = 0; ni < 4; ni++)
            bq[ni] = *reinterpret_cast<const uint4*>(&Bs[cur][bfw[ni]]);
#pragma unroll
        for (int kk = 0; kk < 2; kk++) {
            uint4 aq[4];
#pragma unroll
            for (int mi = 0; mi < 4; mi++)
                aq[mi] = *reinterpret_cast<const uint4*>(&As[cur][afw[mi][kk]]);
#pragma unroll
            for (int mi = 0; mi < 4; mi++) {
                const unsigned* a = reinterpret_cast<const unsigned*>(&aq[mi]);
#pragma unroll
                for (int ni = 0; ni < 4; ni++) {
                    const unsigned* b = reinterpret_cast<const unsigned*>(&bq[ni]);
                    mma8(acc[mi][ni], a, b[2 * kk], b[2 * kk + 1]);
                }
            }
        }

        // store prefetched data into the other buffer
        if (pf) {
            unsigned* da = As[cur ^ 1];
            unsigned* db = Bs[cur ^ 1];
#pragma unroll
            for (int i = 0; i < 4; i++) {
                unsigned* dst = (spart[i] == 0) ? da : db;
                dst[soff[i][0]] = cvt_tf32(pv[i].x);
                dst[soff[i][1]] = cvt_tf32(pv[i].y);
                dst[soff[i][2]] = cvt_tf32(pv[i].z);
                dst[soff[i][3]] = cvt_tf32(pv[i].w);
            }
        }
        __syncthreads();
    }

    // ---- epilogue ----
#pragma unroll
    for (int mi = 0; mi < 4; mi++) {
#pragma unroll
        for (int ni = 0; ni < 4; ni++) {
            int r = m0 + wr * 64 + mi * 16 + gq;
            int c = n0 + wc * 32 + ni * 8 + 2 * tg;
            float2 v0 = make_float2(acc[mi][ni][0], acc[mi][ni][1]);
            float2 v1 = make_float2(acc[mi][ni][2], acc[mi][ni][3]);
            if constexpr (MODE == 0) {
                *reinterpret_cast<float2*>(&g_mid12[(size_t)r * 1024 + c])       = v0;
                *reinterpret_cast<float2*>(&g_mid12[(size_t)(r + 8) * 1024 + c]) = v1;
            } else if constexpr (MODE == 1) {
                *reinterpret_cast<float2*>(&g_outp[(size_t)r * H + c])       = v0;
                *reinterpret_cast<float2*>(&g_outp[(size_t)(r + 8) * H + c]) = v1;
            } else if constexpr (MODE == 2) {
                *reinterpret_cast<float2*>(&g_smid[(size_t)r * (2 * ISZ) + c])       = v0;
                *reinterpret_cast<float2*>(&g_smid[(size_t)(r + 8) * (2 * ISZ) + c]) = v1;
            } else {
                float ga0 = g_gate[r], ga1 = g_gate[r + 8];
                v0.x *= ga0; v0.y *= ga0;
                v1.x *= ga1; v1.y *= ga1;
                *reinterpret_cast<float2*>(&Out[(size_t)r * H + c])       = v0;
                *reinterpret_cast<float2*>(&Out[(size_t)(r + 8) * H + c]) = v1;
            }
        }
    }
}

// ---------------- elementwise -------------------------------------------------
__global__ void swiglu_e() {
    size_t idx = (size_t)blockIdx.x * blockDim.x + threadIdx.x;
    if (idx >= (size_t)MAXROWS * IE) return;
    int row = (int)(idx / IE), i = (int)(idx % IE);
    float v = 0.f;
    if (g_rowtok[row] >= 0) {
        float gv = g_mid12[(size_t)row * 1024 + i];
        float uv = g_mid12[(size_t)row * 1024 + 512 + i];
        v = gv / (1.f + expf(-gv)) * uv * g_roww[row];
    }
    g_hmid[idx] = v;
}

__global__ void swiglu_sh() {
    size_t idx = (size_t)blockIdx.x * blockDim.x + threadIdx.x;
    if (idx >= (size_t)T * ISZ) return;
    int t = (int)(idx / ISZ), i = (int)(idx % ISZ);
    float gv = g_smid[(size_t)t * 2 * ISZ + i];
    float uv = g_smid[(size_t)t * 2 * ISZ + ISZ + i];
    g_shmid[idx] = gv / (1.f + expf(-gv)) * uv;
}

__global__ void final_add(float* __restrict__ out) {
    size_t idx = (size_t)blockIdx.x * blockDim.x + threadIdx.x;
    if (idx >= (size_t)T * H) return;
    int t = (int)(idx / H), h = (int)(idx % H);
    int p0 = g_pairslot[t * 2], p1 = g_pairslot[t * 2 + 1];
    out[idx] += g_outp[(size_t)p0 * H + h] + g_outp[(size_t)p1 * H + h];
}

// ---------------- launch ------------------------------------------------------
extern "C" void kernel_launch(void* const* d_in, const int* in_sizes, int n_in,
                              void* d_out, int out_size) {
    (void)in_sizes; (void)n_in; (void)out_size;
    const float* X   = (const float*)d_in[0];
    const float* GW  = (const float*)d_in[1];
    const float* W1  = (const float*)d_in[2];
    const float* W2  = (const float*)d_in[3];
    const float* W3  = (const float*)d_in[4];
    const float* WSG = (const float*)d_in[5];
    const float* WSU = (const float*)d_in[6];
    const float* WSD = (const float*)d_in[7];
    const float* SGW = (const float*)d_in[8];
    float* out = (float*)d_out;

    zero_init<<<(MAXROWS + 255) / 256, 256>>>();
    router_k<<<T / 4, 128>>>(X, GW, SGW);
    offsets_k<<<1, 32>>>();
    scatter_k<<<(T + 255) / 256, 256>>>();

    // routed experts
    gemm_k<0><<<dim3(1024 / BN, MAXTILES), 256>>>(X, W1, W3, nullptr);
    swiglu_e<<<(MAXROWS * IE) / 256, 256>>>();
    gemm_k<1><<<dim3(H / BN, MAXTILES), 256>>>(nullptr, W2, nullptr, nullptr);

    // shared expert (writes base of d_out)
    gemm_k<2><<<dim3((2 * ISZ) / BN, T / BM), 256>>>(X, WSG, WSU, nullptr);
    swiglu_sh<<<(T * ISZ) / 256, 256>>>();
    gemm_k<3><<<dim3(H / BN, T / BM), 256>>>(nullptr, WSD, nullptr, out);

    // out += routed expert contributions (deterministic, no float atomics)
    final_add<<<(T * H) / 256, 256>>>(out);
}

// round 8
// speedup vs baseline: 1.4852x; 1.4852x over previous
#include <cuda_runtime.h>
#include <cuda_fp16.h>
#include <cstdint>

#define DINLINE __device__ __forceinline__

constexpr int T   = 2048;   // tokens
constexpr int H   = 2048;   // hidden
constexpr int NE  = 16;     // experts
constexpr int IE  = 512;    // expert intermediate
constexpr int ISZ = 2048;   // shared intermediate
constexpr int MAXROWS  = 6144;  // 4096 pairs + 16*128 tile padding
constexpr int MAXTILES = 48;

constexpr int BM = 128, BN = 128, BK = 16;
constexpr int PW = 10;      // padded stride in half2 words (8 data + 2 pad)

// ---------------- scratch (device globals; no allocation allowed) ------------
__device__ int   g_counts[NE];
__device__ int   g_off[NE];
__device__ int   g_cursor[NE];
__device__ int   g_tile_expert[MAXTILES];
__device__ int   g_rowtok[MAXROWS];
__device__ float g_roww[MAXROWS];
__device__ int   g_sel[T * 2];
__device__ float g_wk[T * 2];
__device__ int   g_pairslot[T * 2];
__device__ float g_gate[T];
__device__ float g_mid12[(size_t)MAXROWS * 1024];   // expert gate|up raw
__device__ float g_hmid [(size_t)MAXROWS * IE];     // expert swiglu * weight
__device__ float g_outp [(size_t)MAXROWS * H];      // expert partial outputs
__device__ float g_smid [(size_t)T * 2 * ISZ];      // shared gate|up raw
__device__ float g_shmid[(size_t)T * ISZ];          // shared swiglu

// ---------------- small kernels ---------------------------------------------
__global__ void zero_init() {
    int i = blockIdx.x * blockDim.x + threadIdx.x;
    if (i < MAXROWS) { g_rowtok[i] = -1; g_roww[i] = 0.f; }
    if (i < NE) g_counts[i] = 0;
}

// One warp per token: 16 router logits + 1 shared-gate logit.
__global__ void router_k(const float* __restrict__ X,
                         const float* __restrict__ GW,
                         const float* __restrict__ SGW) {
    __shared__ float Ws[17][128];
    int lane = threadIdx.x & 31, warp = threadIdx.x >> 5;
    int t = blockIdx.x * 4 + warp;

    float acc[17];
#pragma unroll
    for (int e = 0; e < 17; e++) acc[e] = 0.f;

    for (int k0 = 0; k0 < H; k0 += 128) {
        __syncthreads();
        for (int j = threadIdx.x; j < 17 * 128; j += 128) {
            int e = j >> 7, kk = j & 127;
            Ws[e][kk] = (e < 16) ? GW[e * H + k0 + kk] : SGW[k0 + kk];
        }
        __syncthreads();
        float xv[4];
#pragma unroll
        for (int i = 0; i < 4; i++) xv[i] = X[(size_t)t * H + k0 + i * 32 + lane];
#pragma unroll
        for (int e = 0; e < 17; e++) {
#pragma unroll
            for (int i = 0; i < 4; i++) acc[e] += xv[i] * Ws[e][i * 32 + lane];
        }
    }
#pragma unroll
    for (int e = 0; e < 17; e++) {
        float v = acc[e];
#pragma unroll
        for (int o = 16; o > 0; o >>= 1) v += __shfl_xor_sync(0xffffffffu, v, o);
        acc[e] = v;
    }
    if (lane == 0) {
        int i1 = 0;
        for (int e = 1; e < 16; e++) if (acc[e] > acc[i1]) i1 = e;
        int i2 = (i1 == 0) ? 1 : 0;
        for (int e = 0; e < 16; e++) if (e != i1 && acc[e] > acc[i2]) i2 = e;
        float m  = acc[i1];
        float e1 = expf(acc[i1] - m), e2 = expf(acc[i2] - m);
        float s  = e1 + e2;
        g_sel[t * 2] = i1;  g_sel[t * 2 + 1] = i2;
        g_wk [t * 2] = e1 / s;  g_wk [t * 2 + 1] = e2 / s;
        atomicAdd(&g_counts[i1], 1);
        atomicAdd(&g_counts[i2], 1);
        g_gate[t] = 1.f / (1.f + expf(-acc[16]));
    }
}

__global__ void offsets_k() {
    if (threadIdx.x == 0 && blockIdx.x == 0) {
        int off = 0, tile = 0;
        for (int e = 0; e < NE; e++) {
            g_off[e] = off;
            g_cursor[e] = 0;
            int nt = (g_counts[e] + BM - 1) / BM;
            for (int j = 0; j < nt; j++) g_tile_expert[tile++] = e;
            off += nt * BM;
        }
        for (; tile < MAXTILES; tile++) g_tile_expert[tile] = -1;
    }
}

__global__ void scatter_k() {
    int t = blockIdx.x * blockDim.x + threadIdx.x;
    if (t >= T) return;
#pragma unroll
    for (int k = 0; k < 2; k++) {
        int e   = g_sel[t * 2 + k];
        int pos = atomicAdd(&g_cursor[e], 1);
        int row = g_off[e] + pos;
        g_rowtok[row] = t;
        g_roww[row]   = g_wk[t * 2 + k];
        g_pairslot[t * 2 + k] = row;
    }
}

// ---------------- fp16 MMA GEMM ----------------------------------------------
DINLINE unsigned h2pack(float x, float y) {
    __half2 h = __floats2half2_rn(x, y);
    return *reinterpret_cast<unsigned*>(&h);
}
DINLINE void mma16(float* c, const unsigned* a, unsigned b0, unsigned b1) {
    asm volatile(
        "mma.sync.aligned.m16n8k16.row.col.f32.f16.f16.f32 "
        "{%0,%1,%2,%3}, {%4,%5,%6,%7}, {%8,%9}, {%0,%1,%2,%3};"
        : "+f"(c[0]), "+f"(c[1]), "+f"(c[2]), "+f"(c[3])
        : "r"(a[0]), "r"(a[1]), "r"(a[2]), "r"(a[3]), "r"(b0), "r"(b1));
}

// Smem: rows of 8 half2 words (16 halfs = one BK slab), padded stride PW=10.
// MODE 0: expert gate/up  C[row,1024] = Xg[row,H]   * [w1;w3]^T   (gathered rows)
// MODE 1: expert down     C[row,H]    = hmid[row,I] * w2^T
// MODE 2: shared gate/up  C[t,4096]   = X[t,H]      * [wsg;wsu]^T
// MODE 3: shared down     out[t,H]    = gate[t] * (shmid[t,IS] * wsd^T)
template <int MODE>
__global__ void __launch_bounds__(256, 1)
gemm_k(const float* __restrict__ Ain, const float* __restrict__ Wa,
       const float* __restrict__ Wb, float* __restrict__ Out) {
    __shared__ __align__(16) unsigned As[2][BM * PW];
    __shared__ __align__(16) unsigned Bs[2][BN * PW];

    int by = blockIdx.y, bx = blockIdx.x;
    int e = 0;
    if (MODE == 0 || MODE == 1) {
        e = g_tile_expert[by];
        if (e < 0) return;
    }
    const int m0 = by * BM, n0 = bx * BN;
    const int tid = threadIdx.x;
    const int arow = tid >> 1, acol = (tid & 1) * 8;   // 8 floats per thread

    constexpr int KS = (MODE == 1) ? IE : ((MODE == 3) ? ISZ : H);
    constexpr int ksteps = KS / BK;

    const float* aptr = nullptr;
    if constexpr (MODE == 0) {
        int tok = g_rowtok[m0 + arow];
        if (tok >= 0) aptr = Ain + (size_t)tok * H + acol;
    } else if constexpr (MODE == 1) {
        aptr = g_hmid + (size_t)(m0 + arow) * IE + acol;
    } else if constexpr (MODE == 2) {
        aptr = Ain + (size_t)(m0 + arow) * H + acol;
    } else {
        aptr = g_shmid + (size_t)(m0 + arow) * ISZ + acol;
    }

    int n = n0 + arow;
    const float* bptr;
    if constexpr (MODE == 0)
        bptr = ((n < IE) ? (Wa + ((size_t)e * IE + n) * H)
                         : (Wb + ((size_t)e * IE + (n - IE)) * H)) + acol;
    else if constexpr (MODE == 1)
        bptr = Wa + ((size_t)e * H + n) * IE + acol;
    else if constexpr (MODE == 2)
        bptr = ((n < ISZ) ? (Wa + (size_t)n * H) : (Wb + (size_t)(n - ISZ) * H)) + acol;
    else
        bptr = Wa + (size_t)n * ISZ + acol;

    float acc[4][4][4];
#pragma unroll
    for (int i = 0; i < 4; i++)
#pragma unroll
        for (int j = 0; j < 4; j++)
#pragma unroll
            for (int k = 0; k < 4; k++) acc[i][j][k] = 0.f;

    const int wid = tid >> 5, lane = tid & 31;
    const int wr = wid >> 2, wc = wid & 3;   // 2x4 warp grid, warp tile 64x32
    const int gq = lane >> 2, tg = lane & 3;

    const int sdst = arow * PW + acol / 2;   // word offset for this thread's stores
    const float4 z4 = make_float4(0.f, 0.f, 0.f, 0.f);

    // ---- stage 0 ----
    {
        float4 a0 = aptr ? *reinterpret_cast<const float4*>(aptr)     : z4;
        float4 a1 = aptr ? *reinterpret_cast<const float4*>(aptr + 4) : z4;
        float4 b0 = *reinterpret_cast<const float4*>(bptr);
        float4 b1 = *reinterpret_cast<const float4*>(bptr + 4);
        uint2 al = make_uint2(h2pack(a0.x, a0.y), h2pack(a0.z, a0.w));
        uint2 ah = make_uint2(h2pack(a1.x, a1.y), h2pack(a1.z, a1.w));
        uint2 bl = make_uint2(h2pack(b0.x, b0.y), h2pack(b0.z, b0.w));
        uint2 bh = make_uint2(h2pack(b1.x, b1.y), h2pack(b1.z, b1.w));
        *reinterpret_cast<uint2*>(&As[0][sdst])     = al;
        *reinterpret_cast<uint2*>(&As[0][sdst + 2]) = ah;
        *reinterpret_cast<uint2*>(&Bs[0][sdst])     = bl;
        *reinterpret_cast<uint2*>(&Bs[0][sdst + 2]) = bh;
    }
    if (aptr) aptr += BK;
    bptr += BK;
    __syncthreads();

#pragma unroll 1
    for (int kt = 0; kt < ksteps; ++kt) {
        int cur = kt & 1;
        bool pf = (kt + 1) < ksteps;
        float4 a0, a1, b0, b1;
        if (pf) {
            a0 = aptr ? *reinterpret_cast<const float4*>(aptr)     : z4;
            a1 = aptr ? *reinterpret_cast<const float4*>(aptr + 4) : z4;
            b0 = *reinterpret_cast<const float4*>(bptr);
            b1 = *reinterpret_cast<const float4*>(bptr + 4);
            if (aptr) aptr += BK;
            bptr += BK;
        }

        const unsigned* Ab = As[cur];
        const unsigned* Bb = Bs[cur];
        unsigned af[4][4], bf[4][2];
#pragma unroll
        for (int mi = 0; mi < 4; mi++) {
            int r = wr * 64 + mi * 16 + gq;
            const unsigned* p = Ab + r * PW + tg;
            af[mi][0] = p[0];
            af[mi][1] = p[8 * PW];
            af[mi][2] = p[4];
            af[mi][3] = p[8 * PW + 4];
        }
#pragma unroll
        for (int ni = 0; ni < 4; ni++) {
            int nn = wc * 32 + ni * 8 + gq;
            const unsigned* p = Bb + nn * PW + tg;
            bf[ni][0] = p[0];
            bf[ni][1] = p[4];
        }
#pragma unroll
        for (int mi = 0; mi < 4; mi++)
#pragma unroll
            for (int ni = 0; ni < 4; ni++)
                mma16(acc[mi][ni], af[mi], bf[ni][0], bf[ni][1]);

        if (pf) {
            unsigned* da = &As[cur ^ 1][sdst];
            unsigned* db = &Bs[cur ^ 1][sdst];
            uint2 al = make_uint2(h2pack(a0.x, a0.y), h2pack(a0.z, a0.w));
            uint2 ah = make_uint2(h2pack(a1.x, a1.y), h2pack(a1.z, a1.w));
            uint2 bl = make_uint2(h2pack(b0.x, b0.y), h2pack(b0.z, b0.w));
            uint2 bh = make_uint2(h2pack(b1.x, b1.y), h2pack(b1.z, b1.w));
            *reinterpret_cast<uint2*>(da)     = al;
            *reinterpret_cast<uint2*>(da + 2) = ah;
            *reinterpret_cast<uint2*>(db)     = bl;
            *reinterpret_cast<uint2*>(db + 2) = bh;
        }
        __syncthreads();
    }

    // ---- epilogue (C fragment layout identical to tf32 path) ----
#pragma unroll
    for (int mi = 0; mi < 4; mi++) {
#pragma unroll
        for (int ni = 0; ni < 4; ni++) {
            int r = m0 + wr * 64 + mi * 16 + gq;
            int c = n0 + wc * 32 + ni * 8 + 2 * tg;
            float2 v0 = make_float2(acc[mi][ni][0], acc[mi][ni][1]);
            float2 v1 = make_float2(acc[mi][ni][2], acc[mi][ni][3]);
            if constexpr (MODE == 0) {
                *reinterpret_cast<float2*>(&g_mid12[(size_t)r * 1024 + c])       = v0;
                *reinterpret_cast<float2*>(&g_mid12[(size_t)(r + 8) * 1024 + c]) = v1;
            } else if constexpr (MODE == 1) {
                *reinterpret_cast<float2*>(&g_outp[(size_t)r * H + c])       = v0;
                *reinterpret_cast<float2*>(&g_outp[(size_t)(r + 8) * H + c]) = v1;
            } else if constexpr (MODE == 2) {
                *reinterpret_cast<float2*>(&g_smid[(size_t)r * (2 * ISZ) + c])       = v0;
                *reinterpret_cast<float2*>(&g_smid[(size_t)(r + 8) * (2 * ISZ) + c]) = v1;
            } else {
                float ga0 = g_gate[r], ga1 = g_gate[r + 8];
                v0.x *= ga0; v0.y *= ga0;
                v1.x *= ga1; v1.y *= ga1;
                *reinterpret_cast<float2*>(&Out[(size_t)r * H + c])       = v0;
                *reinterpret_cast<float2*>(&Out[(size_t)(r + 8) * H + c]) = v1;
            }
        }
    }
}

// ---------------- elementwise -------------------------------------------------
__global__ void swiglu_e() {
    size_t idx = (size_t)blockIdx.x * blockDim.x + threadIdx.x;
    if (idx >= (size_t)MAXROWS * IE) return;
    int row = (int)(idx / IE), i = (int)(idx % IE);
    float v = 0.f;
    if (g_rowtok[row] >= 0) {
        float gv = g_mid12[(size_t)row * 1024 + i];
        float uv = g_mid12[(size_t)row * 1024 + 512 + i];
        v = gv / (1.f + expf(-gv)) * uv * g_roww[row];
    }
    g_hmid[idx] = v;
}

__global__ void swiglu_sh() {
    size_t idx = (size_t)blockIdx.x * blockDim.x + threadIdx.x;
    if (idx >= (size_t)T * ISZ) return;
    int t = (int)(idx / ISZ), i = (int)(idx % ISZ);
    float gv = g_smid[(size_t)t * 2 * ISZ + i];
    float uv = g_smid[(size_t)t * 2 * ISZ + ISZ + i];
    g_shmid[idx] = gv / (1.f + expf(-gv)) * uv;
}

__global__ void final_add(float* __restrict__ out) {
    size_t idx = (size_t)blockIdx.x * blockDim.x + threadIdx.x;
    if (idx >= (size_t)T * H) return;
    int t = (int)(idx / H), h = (int)(idx % H);
    int p0 = g_pairslot[t * 2], p1 = g_pairslot[t * 2 + 1];
    out[idx] += g_outp[(size_t)p0 * H + h] + g_outp[(size_t)p1 * H + h];
}

// ---------------- launch ------------------------------------------------------
extern "C" void kernel_launch(void* const* d_in, const int* in_sizes, int n_in,
                              void* d_out, int out_size) {
    (void)in_sizes; (void)n_in; (void)out_size;
    const float* X   = (const float*)d_in[0];
    const float* GW  = (const float*)d_in[1];
    const float* W1  = (const float*)d_in[2];
    const float* W2  = (const float*)d_in[3];
    const float* W3  = (const float*)d_in[4];
    const float* WSG = (const float*)d_in[5];
    const float* WSU = (const float*)d_in[6];
    const float* WSD = (const float*)d_in[7];
    const float* SGW = (const float*)d_in[8];
    float* out = (float*)d_out;

    zero_init<<<(MAXROWS + 255) / 256, 256>>>();
    router_k<<<T / 4, 128>>>(X, GW, SGW);
    offsets_k<<<1, 32>>>();
    scatter_k<<<(T + 255) / 256, 256>>>();

    // routed experts
    gemm_k<0><<<dim3(1024 / BN, MAXTILES), 256>>>(X, W1, W3, nullptr);
    swiglu_e<<<(MAXROWS * IE) / 256, 256>>>();
    gemm_k<1><<<dim3(H / BN, MAXTILES), 256>>>(nullptr, W2, nullptr, nullptr);

    // shared expert (writes base of d_out)
    gemm_k<2><<<dim3((2 * ISZ) / BN, T / BM), 256>>>(X, WSG, WSU, nullptr);
    swiglu_sh<<<(T * ISZ) / 256, 256>>>();
    gemm_k<3><<<dim3(H / BN, T / BM), 256>>>(nullptr, WSD, nullptr, out);

    // out += routed expert contributions (deterministic, no float atomics)
    final_add<<<(T * H) / 256, 256>>>(out);
}